// round 15
// baseline (speedup 1.0000x reference)
#include <cuda_runtime.h>
#include <math.h>
#include <stdint.h>

#define Bn   64
#define Sn   128
#define Vn   32000
#define En   256
#define EHn  512
#define Hn   512
#define An   256
#define KFC  1280   // H + Eh + E
#define G3   1536   // 3*H

// ---- scratch (allocation-free: __device__ globals) ----
__device__ float g_embedded[Bn*En];
__device__ float g_dproj[Bn*An];
__device__ float g_context[Bn*EHn];
__device__ float g_gx[Bn*G3];
__device__ float g_gh[Bn*G3];
__device__ float g_act[Bn*KFC];   // row-major [b][k]

__device__ __forceinline__ uint32_t f2tf32(float x) {
    uint32_t r;
    asm("cvt.rna.tf32.f32 %0, %1;" : "=r"(r) : "f"(x));
    return r;
}
__device__ __forceinline__ void mma_tf32_16x8x8(float& c0, float& c1, float& c2, float& c3,
                                                uint32_t a0, uint32_t a1, uint32_t a2, uint32_t a3,
                                                uint32_t b0, uint32_t b1) {
    asm("mma.sync.aligned.m16n8k8.row.col.f32.tf32.tf32.f32 "
        "{%0,%1,%2,%3}, {%4,%5,%6,%7}, {%8,%9}, {%0,%1,%2,%3};"
        : "+f"(c0), "+f"(c1), "+f"(c2), "+f"(c3)
        : "r"(a0), "r"(a1), "r"(a2), "r"(a3), "r"(b0), "r"(b1));
}
__device__ __forceinline__ void cp_async16(void* smem_ptr, const void* gptr) {
    uint32_t sa = (uint32_t)__cvta_generic_to_shared(smem_ptr);
    asm volatile("cp.async.cg.shared.global [%0], [%1], 16;" :: "r"(sa), "l"(gptr));
}
#define CP_COMMIT() asm volatile("cp.async.commit_group;")
#define CP_WAIT3()  asm volatile("cp.async.wait_group 3;")
#define CP_WAIT1()  asm volatile("cp.async.wait_group 1;")
#define CP_WAIT0()  asm volatile("cp.async.wait_group 0;")

// ============================================================
// K0: embedded = emb[tgt];  dproj = hidden @ Wa_dec + ba
// ============================================================
__global__ void k0_embed_dproj(const int* __restrict__ tgt,
                               const float* __restrict__ hidden,
                               const float* __restrict__ emb,
                               const float* __restrict__ Wa_dec,
                               const float* __restrict__ ba) {
    int b = blockIdx.x;
    int a = threadIdx.x;
    __shared__ float h_s[Hn];
    for (int i = threadIdx.x; i < Hn; i += 256) h_s[i] = hidden[b*Hn + i];

    int tok = tgt[b];
    float ev = emb[(size_t)tok*En + a];
    g_embedded[b*En + a] = ev;
    g_act[b*KFC + Hn + EHn + a] = ev;
    __syncthreads();

    float a0 = ba[a], a1 = 0.f, a2 = 0.f, a3 = 0.f;
    #pragma unroll 4
    for (int h = 0; h < Hn; h += 4) {
        a0 += h_s[h  ] * Wa_dec[(h  )*An + a];
        a1 += h_s[h+1] * Wa_dec[(h+1)*An + a];
        a2 += h_s[h+2] * Wa_dec[(h+2)*An + a];
        a3 += h_s[h+3] * Wa_dec[(h+3)*An + a];
    }
    g_dproj[b*An + a] = (a0 + a1) + (a2 + a3);
}

// ============================================================
// K12: FUSED energy GEMM + tanh/dot + softmax + context.
// grid 64 (one block per b), 256 thr.  M=128 (all s), N=256, K=512.
// A (enc) register-staged, stored tf32.  B (Wa_enc) cp.async double-buffer.
// Epilogue barriers are uniform (no __syncthreads in divergent code).
// ============================================================
#define K12_KC 16
#define K12_AP 20
#define K12_BP 264
#define K12_NCH 32

__global__ __launch_bounds__(256, 1)
void k12_energy_softmax_ctx(const float* __restrict__ enc,
                            const float* __restrict__ Wa_enc,
                            const float* __restrict__ v_att,
                            const int* __restrict__ mask,
                            float* __restrict__ out_attn) {
    int b = blockIdx.x;
    int lane = threadIdx.x & 31;
    int warp = threadIdx.x >> 5;
    int qid = lane >> 2, ql = lane & 3;
    int n0 = warp * 32;

    __shared__ __align__(16) uint32_t As[128 * K12_AP];       // 10240 B (tf32)
    __shared__ __align__(16) float Bs[2][K12_KC * K12_BP];    // 33792 B
    __shared__ float at_s[Sn];
    __shared__ float redm[4], reds[4];
    float (*red)[8] = (float(*)[8])As;                        // overlay (As dead post-loop)

    auto ldA = [&](int c, float4 ar[2]) {
        int kc = c << 4;
        #pragma unroll
        for (int r = 0; r < 2; r++) {
            int q = threadIdx.x + 256*r;                 // 512 quads: 128 rows x 4
            int m = q >> 2, k4 = (q & 3) << 2;
            ar[r] = __ldg((const float4*)&enc[((size_t)(b*Sn + m))*EHn + kc + k4]);
        }
    };
    auto stA = [&](float4 ar[2]) {
        #pragma unroll
        for (int r = 0; r < 2; r++) {
            int q = threadIdx.x + 256*r;
            int m = q >> 2, k4 = (q & 3) << 2;
            uint32_t* dst = &As[m*K12_AP + k4];
            dst[0] = f2tf32(ar[r].x); dst[1] = f2tf32(ar[r].y);
            dst[2] = f2tf32(ar[r].z); dst[3] = f2tf32(ar[r].w);
        }
    };
    auto fillB = [&](int c, int buf) {
        int kc = c << 4;
        #pragma unroll
        for (int r = 0; r < 4; r++) {
            int idx = threadIdx.x + 256*r;               // 1024 quads
            int row = idx >> 6, c4 = (idx & 63) << 2;
            cp_async16(&Bs[buf][row*K12_BP + c4], &Wa_enc[(size_t)(kc + row)*An + c4]);
        }
    };

    float acc[8][4][4];
    #pragma unroll
    for (int mi = 0; mi < 8; mi++)
        #pragma unroll
        for (int ni = 0; ni < 4; ni++)
            #pragma unroll
            for (int c = 0; c < 4; c++) acc[mi][ni][c] = 0.f;

    fillB(0, 0); CP_COMMIT();
    { float4 a0r[2]; ldA(0, a0r); stA(a0r); }

    for (int c = 0; c < K12_NCH; c++) {
        int buf = c & 1;
        float4 arn[2];
        bool hasNext = (c + 1 < K12_NCH);
        if (hasNext) {
            ldA(c + 1, arn);
            fillB(c + 1, buf ^ 1); CP_COMMIT();
            CP_WAIT1();
        } else {
            CP_WAIT0();
        }
        __syncthreads();

        #pragma unroll
        for (int kk = 0; kk < K12_KC; kk += 8) {
            uint32_t af[8][4];
            #pragma unroll
            for (int mi = 0; mi < 8; mi++) {
                int m0 = mi*16 + qid;
                af[mi][0] = As[(m0    )*K12_AP + kk + ql    ];
                af[mi][1] = As[(m0 + 8)*K12_AP + kk + ql    ];
                af[mi][2] = As[(m0    )*K12_AP + kk + ql + 4];
                af[mi][3] = As[(m0 + 8)*K12_AP + kk + ql + 4];
            }
            #pragma unroll
            for (int ni = 0; ni < 4; ni++) {
                int nn = n0 + ni*8 + qid;
                uint32_t b0 = f2tf32(Bs[buf][(kk + ql    )*K12_BP + nn]);
                uint32_t b1 = f2tf32(Bs[buf][(kk + ql + 4)*K12_BP + nn]);
                #pragma unroll
                for (int mi = 0; mi < 8; mi++)
                    mma_tf32_16x8x8(acc[mi][ni][0], acc[mi][ni][1], acc[mi][ni][2], acc[mi][ni][3],
                                    af[mi][0], af[mi][1], af[mi][2], af[mi][3], b0, b1);
            }
        }
        __syncthreads();

        if (hasNext) stA(arn);
    }

    // ---- epilogue 1: tanh(acc + dproj) . v_att, reduce over a ----
    float part[8][2];
    #pragma unroll
    for (int mi = 0; mi < 8; mi++) { part[mi][0] = 0.f; part[mi][1] = 0.f; }
    #pragma unroll
    for (int ni = 0; ni < 4; ni++) {
        int col = n0 + ni*8 + 2*ql;
        float2 dp = *(const float2*)&g_dproj[b*An + col];
        float2 va = *(const float2*)&v_att[col];
        #pragma unroll
        for (int mi = 0; mi < 8; mi++) {
            part[mi][0] += tanhf(acc[mi][ni][0] + dp.x)*va.x + tanhf(acc[mi][ni][1] + dp.y)*va.y;
            part[mi][1] += tanhf(acc[mi][ni][2] + dp.x)*va.x + tanhf(acc[mi][ni][3] + dp.y)*va.y;
        }
    }
    #pragma unroll
    for (int mi = 0; mi < 8; mi++) {
        #pragma unroll
        for (int h = 0; h < 2; h++) {
            float p = part[mi][h];
            p += __shfl_xor_sync(0xffffffffu, p, 1);
            p += __shfl_xor_sync(0xffffffffu, p, 2);
            if (ql == 0) red[mi*16 + h*8 + qid][warp] = p;
        }
    }
    __syncthreads();

    // ---- epilogue 2: softmax over 128 scores.  UNIFORM barriers. ----
    int t = threadIdx.x;
    if (t < 128) {
        float s = 0.f;
        #pragma unroll
        for (int w = 0; w < 8; w++) s += red[t][w];
        float v = mask[b*Sn + t] ? s : -1e9f;
        at_s[t] = v;
        float m = v;
        #pragma unroll
        for (int o = 16; o > 0; o >>= 1) m = fmaxf(m, __shfl_xor_sync(0xffffffffu, m, o));
        if (lane == 0) redm[t >> 5] = m;
    }
    __syncthreads();
    float mglob = fmaxf(fmaxf(redm[0], redm[1]), fmaxf(redm[2], redm[3]));
    float ex = 0.f;
    if (t < 128) {
        ex = __expf(at_s[t] - mglob);
        float sm = ex;
        #pragma unroll
        for (int o = 16; o > 0; o >>= 1) sm += __shfl_xor_sync(0xffffffffu, sm, o);
        if (lane == 0) reds[t >> 5] = sm;
    }
    __syncthreads();
    if (t < 128) {
        float tot = reds[0] + reds[1] + reds[2] + reds[3];
        float at = ex / tot;
        at_s[t] = at;
        if (out_attn) out_attn[b*Sn + t] = at;
    }
    __syncthreads();

    // ---- epilogue 3: context = attn @ enc (each thread: h = t, t+256) ----
    {
        int h = t;
        float c0 = 0.f, c1 = 0.f, c2 = 0.f, c3 = 0.f;
        float d0 = 0.f, d1 = 0.f, d2 = 0.f, d3 = 0.f;
        #pragma unroll 4
        for (int s = 0; s < Sn; s += 4) {
            const float* e0 = &enc[((size_t)(b*Sn + s))*EHn + h];
            float a0 = at_s[s], a1 = at_s[s+1], a2 = at_s[s+2], a3 = at_s[s+3];
            c0 += a0 * e0[0];
            c1 += a1 * e0[EHn];
            c2 += a2 * e0[2*EHn];
            c3 += a3 * e0[3*EHn];
            d0 += a0 * e0[256];
            d1 += a1 * e0[EHn + 256];
            d2 += a2 * e0[2*EHn + 256];
            d3 += a3 * e0[3*EHn + 256];
        }
        float cc = (c0 + c1) + (c2 + c3);
        float dd = (d0 + d1) + (d2 + d3);
        g_context[b*EHn + h] = cc;
        g_act[b*KFC + Hn + h] = cc;
        g_context[b*EHn + h + 256] = dd;
        g_act[b*KFC + Hn + h + 256] = dd;
    }
}

// ============================================================
// K3: gate GEMMs.  A register-staged + stored tf32 (single buffer);
// B cp.async double-buffer, cvt at use.  grid (48 j-tiles of 32, 2 phases).
// ============================================================
#define K3_P 36

__global__ __launch_bounds__(256, 2)
void k3_gates(const float* __restrict__ hidden,
              const float* __restrict__ W_ih, const float* __restrict__ W_hh,
              const float* __restrict__ b_ih, const float* __restrict__ b_hh) {
    int lane = threadIdx.x & 31;
    int warp = threadIdx.x >> 5;
    int qid = lane >> 2, ql = lane & 3;
    int jbase = blockIdx.x * 32;
    int phase = blockIdx.y;
    int n0 = (warp & 3) * 8;
    int mbase = (warp >> 2) * 32;

    const float* W    = phase ? W_hh : W_ih;
    const float* bia  = phase ? b_hh : b_ih;
    float*       gout = phase ? g_gh : g_gx;
    int Kt  = phase ? 512 : 768;
    int NCH = Kt >> 5;

    __shared__ __align__(16) uint32_t As[64 * K3_P];  // tf32, single buffer
    __shared__ __align__(16) float Bs[2][32 * K3_P];

    auto ldA = [&](int c, float4 ar[2]) {
        int kc = c << 5;
        #pragma unroll
        for (int r = 0; r < 2; r++) {
            int idx = threadIdx.x + 256*r;               // 512 quads (64 x 8)
            int m = idx >> 3, k4 = (idx & 7) << 2;
            const float* src;
            if (phase) {
                src = &hidden[m*Hn + kc + k4];
            } else {
                int kk = kc + k4;
                src = (kk < En) ? &g_embedded[m*En + kk]
                                : &g_context[m*EHn + (kk - En)];
            }
            ar[r] = __ldg((const float4*)src);
        }
    };
    auto stA = [&](float4 ar[2]) {
        #pragma unroll
        for (int r = 0; r < 2; r++) {
            int idx = threadIdx.x + 256*r;
            int m = idx >> 3, k4 = (idx & 7) << 2;
            uint32_t* dst = &As[m*K3_P + k4];
            dst[0] = f2tf32(ar[r].x); dst[1] = f2tf32(ar[r].y);
            dst[2] = f2tf32(ar[r].z); dst[3] = f2tf32(ar[r].w);
        }
    };
    auto fillB = [&](int c, int buf) {
        int kc = c << 5;
        int j = threadIdx.x >> 3, k4 = (threadIdx.x & 7) << 2;   // 256 quads
        cp_async16(&Bs[buf][j*K3_P + k4], &W[(size_t)(jbase + j)*Kt + kc + k4]);
    };

    float acc[2][4];
    #pragma unroll
    for (int mi = 0; mi < 2; mi++)
        #pragma unroll
        for (int c = 0; c < 4; c++) acc[mi][c] = 0.f;

    fillB(0, 0); CP_COMMIT();
    { float4 a0r[2]; ldA(0, a0r); stA(a0r); }

    for (int c = 0; c < NCH; c++) {
        int buf = c & 1;
        float4 arn[2];
        bool hasNext = (c + 1 < NCH);
        if (hasNext) {
            ldA(c + 1, arn);
            fillB(c + 1, buf ^ 1); CP_COMMIT();
            CP_WAIT1();
        } else {
            CP_WAIT0();
        }
        __syncthreads();

        #pragma unroll
        for (int kk = 0; kk < 32; kk += 8) {
            int nn = n0 + qid;
            uint32_t b0 = f2tf32(Bs[buf][nn*K3_P + kk + ql    ]);
            uint32_t b1 = f2tf32(Bs[buf][nn*K3_P + kk + ql + 4]);
            #pragma unroll
            for (int mi = 0; mi < 2; mi++) {
                int m0 = mbase + mi*16 + qid;
                uint32_t a0 = As[(m0    )*K3_P + kk + ql    ];
                uint32_t a1 = As[(m0 + 8)*K3_P + kk + ql    ];
                uint32_t a2 = As[(m0    )*K3_P + kk + ql + 4];
                uint32_t a3 = As[(m0 + 8)*K3_P + kk + ql + 4];
                mma_tf32_16x8x8(acc[mi][0], acc[mi][1], acc[mi][2], acc[mi][3],
                                a0, a1, a2, a3, b0, b1);
            }
        }
        __syncthreads();

        if (hasNext) stA(arn);
    }

    int j = jbase + n0 + 2*ql;
    float bx = bia[j], by = bia[j + 1];
    #pragma unroll
    for (int mi = 0; mi < 2; mi++) {
        int r0 = mbase + mi*16 + qid;
        *(float2*)&gout[(size_t)(r0    )*G3 + j] = make_float2(acc[mi][0] + bx, acc[mi][1] + by);
        *(float2*)&gout[(size_t)(r0 + 8)*G3 + j] = make_float2(acc[mi][2] + bx, acc[mi][3] + by);
    }
}

// ============================================================
// K3b: GRU combine -> new_hidden.
// ============================================================
__global__ void k3b_gru(const float* __restrict__ hidden, float* __restrict__ out_h) {
    int gid = blockIdx.x*256 + threadIdx.x;
    int b = gid >> 9, i = gid & 511;
    const float* gx = g_gx + b*G3;
    const float* gh = g_gh + b*G3;
    float r = 1.f/(1.f + __expf(-(gx[i]        + gh[i])));
    float z = 1.f/(1.f + __expf(-(gx[Hn + i]   + gh[Hn + i])));
    float n = tanhf(gx[2*Hn + i] + r*gh[2*Hn + i]);
    float nh = (1.f - z)*n + z*hidden[b*Hn + i];
    g_act[b*KFC + i] = nh;
    if (out_h) out_h[b*Hn + i] = nh;
}

// ============================================================
// K4: FC GEMM, tf32 MMA + 4-stage cp.async B pipeline.  As stored tf32.
// grid 250 (v-tiles of 128), 256 thr (8 warps, n16 each).
// ============================================================
#define K4_NT   128
#define K4_KC   16
#define K4_AP   20
#define K4_BP   136
#define K4_NCH  80    // KFC/16

__global__ __launch_bounds__(256, 2)
void k4_fc(const float* __restrict__ W_fc, const float* __restrict__ b_fc,
           float* __restrict__ out) {
    int lane = threadIdx.x & 31;
    int warp = threadIdx.x >> 5;
    int qid  = lane >> 2;
    int ql   = lane & 3;
    int vblk = blockIdx.x * K4_NT;
    int n0   = warp * 16;

    __shared__ __align__(16) uint32_t As[64 * K4_AP];   //  5120 B (tf32)
    __shared__ __align__(16) float Bs[4][K4_KC * K4_BP];

    int amb = threadIdx.x >> 4;               // 0..15
    int akf = threadIdx.x & 15;               // 0..15

    auto fillB = [&](int c) {
        int buf = c & 3;
        int kc = c << 4;
        #pragma unroll
        for (int r = 0; r < 2; r++) {
            int idx = threadIdx.x + 256*r;        // 512 quads
            int row = idx >> 5, c4 = (idx & 31) << 2;
            cp_async16(&Bs[buf][row*K4_BP + c4],
                       &W_fc[(size_t)(kc + row)*Vn + vblk + c4]);
        }
    };

    float acc[4][2][4];
    #pragma unroll
    for (int mi = 0; mi < 4; mi++)
        #pragma unroll
        for (int ni = 0; ni < 2; ni++)
            #pragma unroll
            for (int c = 0; c < 4; c++) acc[mi][ni][c] = 0.f;

    fillB(0); CP_COMMIT();
    fillB(1); CP_COMMIT();
    fillB(2); CP_COMMIT();
    #pragma unroll
    for (int r = 0; r < 4; r++) {
        int m = amb + 16*r;
        As[m*K4_AP + akf] = f2tf32(g_act[m*KFC + akf]);
    }

    for (int c = 0; c < K4_NCH; c++) {
        int buf = c & 3;
        float ar[4];
        bool hasNext = (c + 1 < K4_NCH);
        if (hasNext) {
            int kc1 = (c + 1) << 4;
            #pragma unroll
            for (int r = 0; r < 4; r++) {
                int m = amb + 16*r;
                ar[r] = g_act[m*KFC + kc1 + akf];
            }
        }
        if (c + 3 < K4_NCH) {
            fillB(c + 3); CP_COMMIT();
            CP_WAIT3();
        } else {
            CP_WAIT0();
        }
        __syncthreads();

        #pragma unroll
        for (int kk = 0; kk < K4_KC; kk += 8) {
            uint32_t af[4][4];
            #pragma unroll
            for (int mi = 0; mi < 4; mi++) {
                int m0 = mi*16 + qid;
                af[mi][0] = As[(m0    )*K4_AP + kk + ql    ];
                af[mi][1] = As[(m0 + 8)*K4_AP + kk + ql    ];
                af[mi][2] = As[(m0    )*K4_AP + kk + ql + 4];
                af[mi][3] = As[(m0 + 8)*K4_AP + kk + ql + 4];
            }
            #pragma unroll
            for (int ni = 0; ni < 2; ni++) {
                int nn = n0 + ni*8 + qid;
                uint32_t b0 = f2tf32(Bs[buf][(kk + ql    )*K4_BP + nn]);
                uint32_t b1 = f2tf32(Bs[buf][(kk + ql + 4)*K4_BP + nn]);
                #pragma unroll
                for (int mi = 0; mi < 4; mi++) {
                    mma_tf32_16x8x8(acc[mi][ni][0], acc[mi][ni][1], acc[mi][ni][2], acc[mi][ni][3],
                                    af[mi][0], af[mi][1], af[mi][2], af[mi][3], b0, b1);
                }
            }
        }
        __syncthreads();

        if (hasNext) {
            #pragma unroll
            for (int r = 0; r < 4; r++) {
                int m = amb + 16*r;
                As[m*K4_AP + akf] = f2tf32(ar[r]);
            }
        }
    }

    #pragma unroll
    for (int ni = 0; ni < 2; ni++) {
        int v = vblk + n0 + ni*8 + 2*ql;
        float bx = b_fc[v], by = b_fc[v + 1];
        #pragma unroll
        for (int mi = 0; mi < 4; mi++) {
            int row0 = mi*16 + qid;
            float2 o0 = make_float2(acc[mi][ni][0] + bx, acc[mi][ni][1] + by);
            float2 o1 = make_float2(acc[mi][ni][2] + bx, acc[mi][ni][3] + by);
            *(float2*)&out[(size_t)(row0    )*Vn + v] = o0;
            *(float2*)&out[(size_t)(row0 + 8)*Vn + v] = o1;
        }
    }
}

// ============================================================
extern "C" void kernel_launch(void* const* d_in, const int* in_sizes, int n_in,
                              void* d_out, int out_size) {
    const int*   tgt    = (const int*)d_in[0];
    const float* hidden = (const float*)d_in[1];
    const float* enc    = (const float*)d_in[2];
    const int*   mask   = (const int*)d_in[3];
    const float* emb    = (const float*)d_in[4];
    const float* Wa_enc = (const float*)d_in[5];
    const float* Wa_dec = (const float*)d_in[6];
    const float* ba     = (const float*)d_in[7];
    const float* v_att  = (const float*)d_in[8];
    const float* W_ih   = (const float*)d_in[9];
    const float* W_hh   = (const float*)d_in[10];
    const float* b_ih   = (const float*)d_in[11];
    const float* b_hh   = (const float*)d_in[12];
    const float* W_fc   = (const float*)d_in[13];
    const float* b_fc   = (const float*)d_in[14];

    float* out_pred = (float*)d_out;
    float* out_h    = nullptr;
    float* out_attn = nullptr;
    if (out_size >= Bn*Vn + Bn*Hn + Bn*Sn) {
        out_h    = out_pred + (size_t)Bn*Vn;
        out_attn = out_h    + (size_t)Bn*Hn;
    }

    k0_embed_dproj<<<Bn, 256>>>(tgt, hidden, emb, Wa_dec, ba);
    k12_energy_softmax_ctx<<<Bn, 256>>>(enc, Wa_enc, v_att, mask, out_attn);
    k3_gates<<<dim3(48, 2), 256>>>(hidden, W_ih, W_hh, b_ih, b_hh);
    k3b_gru<<<128, 256>>>(hidden, out_h);
    k4_fc<<<250, 256>>>(W_fc, b_fc, out_pred);
}